// round 7
// baseline (speedup 1.0000x reference)
#include <cuda_runtime.h>
#include <math.h>

#define NN 8192
#define EMAX 262144

// Scratch (allocation-free rule: device globals)
__device__ int   g_cnt   [NN];
__device__ int   g_fill  [NN];
__device__ int   g_rowptr[NN + 1];
__device__ int   g_col   [EMAX];
__device__ float g_dinv  [NN];
__device__ float g_h2    [NN * 8];
__device__ float g_x2    [NN * 8];

// ---------------------------------------------------------------------------
// 1. zero the two int counters
__global__ void k_zero() {
    int i = blockIdx.x * blockDim.x + threadIdx.x;
    if (i < NN) { g_cnt[i] = 0; g_fill[i] = 0; }
}

// 2. in-degree histogram over dst
__global__ void k_count(const int* __restrict__ ei, int E) {
    int e = blockIdx.x * blockDim.x + threadIdx.x;
    if (e < E) atomicAdd(&g_cnt[ei[E + e]], 1);
}

// 3. single-block exclusive scan of cnt -> rowptr, plus dinv = rsqrt(deg+1)
__global__ void k_scan() {
    __shared__ int sp[256];
    int t = threadIdx.x;                 // 256 threads, 32 elems each
    int base = t * 32;
    int s = 0;
    int pre[32];
#pragma unroll
    for (int k = 0; k < 32; k++) {
        int cv = g_cnt[base + k];
        pre[k] = s;
        g_dinv[base + k] = rsqrtf((float)cv + 1.0f);
        s += cv;
    }
    sp[t] = s;
    __syncthreads();
    for (int o = 1; o < 256; o <<= 1) {  // inclusive Hillis-Steele
        int v = (t >= o) ? sp[t - o] : 0;
        __syncthreads();
        sp[t] += v;
        __syncthreads();
    }
    int off = sp[t] - s;                 // exclusive offset
#pragma unroll
    for (int k = 0; k < 32; k++) g_rowptr[base + k] = off + pre[k];
    if (t == 255) g_rowptr[NN] = sp[255];
}

// 4. CSR fill: bucket src by dst
__global__ void k_fill(const int* __restrict__ ei, int E) {
    int e = blockIdx.x * blockDim.x + threadIdx.x;
    if (e >= E) return;
    int s = ei[e];
    int d = ei[E + e];
    int p = g_rowptr[d] + atomicAdd(&g_fill[d], 1);
    g_col[p] = s;
}

// 5. conv1 gather + bias + ReLU + 16x8 matmul (16 lanes per node, shfl)
__global__ void k_conv1(const float* __restrict__ W1,
                        const float* __restrict__ b1,
                        const float* __restrict__ W2) {
    int tid  = blockIdx.x * blockDim.x + threadIdx.x;
    int n    = tid >> 4;                 // 16 lanes per node
    int f    = tid & 15;
    if (n >= NN) return;
    int lane  = threadIdx.x & 31;
    int gbase = lane & 16;

    float dn  = g_dinv[n];
    int   beg = g_rowptr[n], end = g_rowptr[n + 1];
    float acc = 0.0f;
    for (int e = beg; e < end; e++) {
        int s = g_col[e];
        acc += g_dinv[s] * W1[(size_t)s * 16 + f];
    }
    float xf = fmaxf(dn * acc + dn * dn * W1[(size_t)n * 16 + f] + b1[f], 0.0f);

    float h = 0.0f;
#pragma unroll
    for (int k = 0; k < 16; k++) {
        float xk = __shfl_sync(0xffffffffu, xf, gbase + k);
        h += xk * W2[k * 8 + (f & 7)];
    }
    if (f < 8) g_h2[(size_t)n * 8 + f] = h;
}

// 6. conv2 gather + bias + ReLU (8 lanes per node)
__global__ void k_conv2(const float* __restrict__ b2) {
    int tid = blockIdx.x * blockDim.x + threadIdx.x;
    int n   = tid >> 3;                  // 8 lanes per node
    int j   = tid & 7;
    if (n >= NN) return;

    float dn  = g_dinv[n];
    int   beg = g_rowptr[n], end = g_rowptr[n + 1];
    float acc = 0.0f;
    for (int e = beg; e < end; e++) {
        int s = g_col[e];
        acc += g_dinv[s] * g_h2[(size_t)s * 8 + j];
    }
    float v = dn * acc + dn * dn * g_h2[(size_t)n * 8 + j] + b2[j];
    g_x2[(size_t)n * 8 + j] = fmaxf(v, 0.0f);
}

// 7. orientation head: out[u,v] = sigmoid(ef @ Wfc + bfc); out[v,u] = 1 - it
__global__ void k_edgeout(const int* __restrict__ ue,
                          const float* __restrict__ Wfc,
                          const float* __restrict__ bfc,
                          float* __restrict__ out, int U) {
    int i = blockIdx.x * blockDim.x + threadIdx.x;
    if (i >= U) return;
    int u = ue[2 * i];
    int v = ue[2 * i + 1];
    float s = bfc[0];
#pragma unroll
    for (int f = 0; f < 8; f++) {
        s += g_x2[(size_t)u * 8 + f] * Wfc[f];
        s += g_x2[(size_t)v * 8 + f] * Wfc[8 + f];
    }
    float o = 1.0f / (1.0f + expf(-s));
    out[(size_t)u * NN + v] = o;
    out[(size_t)v * NN + u] = 1.0f - o;
}

extern "C" void kernel_launch(void* const* d_in, const int* in_sizes, int n_in,
                              void* d_out, int out_size) {
    const float* adj = (const float*)d_in[0];
    const float* W1  = (const float*)d_in[1];
    const float* b1  = (const float*)d_in[2];
    const float* W2  = (const float*)d_in[3];
    const float* b2  = (const float*)d_in[4];
    const float* Wfc = (const float*)d_in[5];
    const float* bfc = (const float*)d_in[6];
    const int*   ei  = (const int*)d_in[7];
    const int*   ue  = (const int*)d_in[8];

    int E = in_sizes[7] / 2;
    int U = in_sizes[8] / 2;

    const int B = 256;

    // Fork-join: copy-engine memcpy on the main stream runs concurrently with
    // the SM chain on a side stream -- hardware-disjoint resources.
    // Streams/events created fresh per call (host handles only; intentionally
    // not destroyed so the captured graph stays valid).
    cudaStream_t s2;
    cudaStreamCreateWithFlags(&s2, cudaStreamNonBlocking);
    cudaEvent_t evFork, evChain;
    cudaEventCreateWithFlags(&evFork,  cudaEventDisableTiming);
    cudaEventCreateWithFlags(&evChain, cudaEventDisableTiming);

    // fork
    cudaEventRecord(evFork, 0);
    cudaStreamWaitEvent(s2, evFork, 0);

    // ---- side stream: CSR build + 2 GCN layers on the SMs (~32us) ----
    k_zero <<<(NN + B - 1) / B, B, 0, s2>>>();
    k_count<<<(E + B - 1) / B, B, 0, s2>>>(ei, E);
    k_scan <<<1, 256, 0, s2>>>();
    k_fill <<<(E + B - 1) / B, B, 0, s2>>>(ei, E);
    k_conv1<<<(NN * 16 + B - 1) / B, B, 0, s2>>>(W1, b1, W2);
    k_conv2<<<(NN * 8 + B - 1) / B, B, 0, s2>>>(b2);
    cudaEventRecord(evChain, s2);

    // ---- main stream: 256MB adjacency copy on the COPY ENGINE ----
    cudaMemcpyAsync(d_out, adj, (size_t)out_size * sizeof(float),
                    cudaMemcpyDeviceToDevice, 0);

    // join: edgeout needs both the copy (WAW on d_out) and the chain (x2)
    cudaStreamWaitEvent(0, evChain, 0);
    k_edgeout<<<(U + B - 1) / B, B>>>(ue, Wfc, bfc, (float*)d_out, U);
}